// round 11
// baseline (speedup 1.0000x reference)
#include <cuda_runtime.h>
#include <math.h>

#define N_SUB   4096
#define N_EDGES 65536
#define KTOT    65536          // 2*8*N_SUB
#define KBLOCKS 128            // GEMV k-chunks of 512
#define KCHUNK  512
#define COLCHUNK 1024          // columns per GEMV block (256 thr * float4)
#define VBLOCKS 256            // fully/value blocks (256 elems each)
#define PF_F4   6291456        // 96 MB of pol_W in float4s
#define PF_THREADS (512 * 256)

// ---- scratch (device globals; no allocation allowed) ----
__device__ float g_deg  [N_SUB];
__device__ float g_w    [N_EDGES];
__device__ float g_Tx1  [N_SUB * 4];
__device__ float g_Tx2  [N_SUB * 4];
__device__ float g_conv [N_SUB * 8];
__device__ float g_virt [8];
__device__ float g_fully[KTOT];
__device__ float g_logits[N_SUB];
__device__ float g_vpart[VBLOCKS];
__device__ float g_pfsink;

// ---------------------------------------------------------------- L2 prefetch of pol_W head
// Fires the programmatic trigger at entry so PSS successors launch immediately
// and overlap with this kernel's streaming reads.
__global__ void __launch_bounds__(256)
k_prefetch(const float* __restrict__ W) {
    cudaTriggerProgrammaticLaunchCompletion();
    int tid = blockIdx.x * blockDim.x + threadIdx.x;
    const float4* p = reinterpret_cast<const float4*>(W);
    float4 a = make_float4(0.f, 0.f, 0.f, 0.f);
#pragma unroll 4
    for (size_t i = tid; i < PF_F4; i += PF_THREADS) {
        float4 v = __ldcg(p + i);
        a.x += v.x; a.y += v.y; a.z += v.z; a.w += v.w;
    }
    if (a.x + a.y + a.z + a.w == 123456789.0f) g_pfsink = 1.f;  // keep loads live
}

// ---------------------------------------------------------------- zero + logits=bias
__global__ void k_zero(const float* __restrict__ pol_b) {
    cudaGridDependencySynchronize();   // predecessor (prefetch) triggered at entry
    int i = blockIdx.x * blockDim.x + threadIdx.x;
    if (i < N_SUB) { g_deg[i] = 0.f; g_logits[i] = pol_b[i]; }
    if (i < N_SUB * 4) { g_Tx1[i] = 0.f; g_Tx2[i] = 0.f; }
}

// ---------------------------------------------------------------- degree (1 edge/thread)
__global__ void k_deg(const int* __restrict__ ei) {
    cudaGridDependencySynchronize();   // wait k_zero's writes (flush) before counting
    int e = blockIdx.x * blockDim.x + threadIdx.x;
    if (e >= N_EDGES) return;
    int s = ei[e];
    if ((unsigned)s < N_SUB) atomicAdd(&g_deg[s], 1.0f);
}

// ---------------------------------------------------------------- L_hat stage 0
// 4 threads per edge; lane f==0 caches w[e] for stage 1.
__global__ void k_lhat0(const int* __restrict__ ei,
                        const float* __restrict__ subs_x) {
    cudaGridDependencySynchronize();   // wait k_deg's atomics
    int tid = blockIdx.x * blockDim.x + threadIdx.x;
    int e = tid >> 2, f = tid & 3;
    if (e >= N_EDGES) return;
    int s = ei[e];
    int d = ei[N_EDGES + e];
    bool ok = (unsigned)s < N_SUB && (unsigned)d < N_SUB;
    float w = 0.f;
    if (ok) {
        float ds = g_deg[s], dd = g_deg[d];
        if (ds > 0.f && dd > 0.f) w = -rsqrtf(ds) * rsqrtf(dd);
    }
    if (f == 0) g_w[e] = w;
    if (w != 0.f)
        atomicAdd(&g_Tx1[d * 4 + f], w * subs_x[s * 4 + f]);
}

// ---------------------------------------------------------------- L_hat stage 1 (cached w)
__global__ void k_lhat1(const int* __restrict__ ei) {
    cudaGridDependencySynchronize();   // wait k_lhat0's Tx1/w writes
    int tid = blockIdx.x * blockDim.x + threadIdx.x;
    int e = tid >> 2, f = tid & 3;
    if (e >= N_EDGES) return;
    float w = g_w[e];
    if (w == 0.f) return;
    int s = ei[e];
    int d = ei[N_EDGES + e];
    atomicAdd(&g_Tx2[d * 4 + f], w * g_Tx1[s * 4 + f]);
}

// ---------------------------------------------------------------- conv + virt (1 node/thread, 64x64)
__global__ void k_conv(const float* __restrict__ subs_x,
                       const float* __restrict__ cheb_W,   // [3,4,8]
                       const float* __restrict__ cheb_b,   // [8]
                       const float* __restrict__ vnr_x,    // [5,2]
                       const float* __restrict__ vnr_W,    // [2,8]
                       const float* __restrict__ vnr_b,    // [8]
                       const int*   __restrict__ j_ptr) {
    cudaGridDependencySynchronize();   // wait k_lhat1's Tx2 writes
    __shared__ float sW[96], sb[8];
    int t = threadIdx.x;
    if (t < 8)  sb[t] = cheb_b[t];
    if (t < 64) { sW[t] = cheb_W[t]; if (t < 32) sW[64 + t] = cheb_W[64 + t]; }
    __syncthreads();

    if (blockIdx.x == 0 && t < 8) {
        int jj = j_ptr[0];
        if ((unsigned)jj >= 5u) jj = 0;
        g_virt[t] = vnr_x[jj * 2 + 0] * vnr_W[t] +
                    vnr_x[jj * 2 + 1] * vnr_W[8 + t] + vnr_b[t];
    }

    int n = blockIdx.x * blockDim.x + t;
    if (n >= N_SUB) return;
    float4 x0 = *reinterpret_cast<const float4*>(subs_x + n * 4);
    float4 x1 = *reinterpret_cast<const float4*>(g_Tx1 + n * 4);
    float4 a2 = *reinterpret_cast<const float4*>(g_Tx2 + n * 4);
    float t0[4] = { x0.x, x0.y, x0.z, x0.w };
    float t1[4] = { x1.x, x1.y, x1.z, x1.w };
    float t2[4] = { 2.f * a2.x - x0.x, 2.f * a2.y - x0.y,
                    2.f * a2.z - x0.z, 2.f * a2.w - x0.w };
#pragma unroll
    for (int o = 0; o < 8; ++o) {
        float s = sb[o];
#pragma unroll
        for (int f = 0; f < 4; ++f) {
            s = fmaf(t0[f], sW[f * 8 + o], s);
            s = fmaf(t1[f], sW[32 + f * 8 + o], s);
            s = fmaf(t2[f], sW[64 + f * 8 + o], s);
        }
        g_conv[n * 8 + o] = fmaxf(s, 0.f);
    }
}

// ---------------------------------------------------------------- perm gather + tanh + value partial dot
__global__ void k_fullyval(const int* __restrict__ perm,
                           const float* __restrict__ val_W) {
    cudaGridDependencySynchronize();   // wait k_conv's conv/virt writes
    __shared__ float sred[8];
    int t = threadIdx.x;
    int i = blockIdx.x * 256 + t;
    int p = perm[i] & (KTOT - 1);
    float v = (p < 8 * N_SUB) ? g_virt[p & 7] : g_conv[p - 8 * N_SUB];
    v = tanhf(v);
    g_fully[i] = v;
    float s = v * val_W[i];
#pragma unroll
    for (int o = 16; o; o >>= 1) s += __shfl_xor_sync(0xffffffffu, s, o);
    if ((t & 31) == 0) sred[t >> 5] = s;
    __syncthreads();
    if (t < 8) {
        float x = sred[t];
#pragma unroll
        for (int o = 4; o; o >>= 1) x += __shfl_xor_sync(0xffu, x, o);
        if (t == 0) g_vpart[blockIdx.x] = x;
    }
}

// ---------------------------------------------------------------- GEMV (accumulate into logits via RED)
// Normal launch: waits for prefetch AND whole prologue to complete+flush.
__global__ void __launch_bounds__(256, 4)
k_gemv(const float* __restrict__ W) {
    __shared__ float sx[KCHUNK];
    int t = threadIdx.x;
    int k0 = blockIdx.y * KCHUNK;
    int col = blockIdx.x * COLCHUNK + t * 4;
    sx[t]       = g_fully[k0 + t];
    sx[t + 256] = g_fully[k0 + t + 256];
    __syncthreads();

    const float* Wp = W + (size_t)k0 * N_SUB + col;
    float4 acc = make_float4(0.f, 0.f, 0.f, 0.f);
#pragma unroll 8
    for (int kk = 0; kk < KCHUNK; ++kk) {
        float xv = sx[kk];
        float4 w = __ldcs(reinterpret_cast<const float4*>(Wp));
        acc.x = fmaf(xv, w.x, acc.x);
        acc.y = fmaf(xv, w.y, acc.y);
        acc.z = fmaf(xv, w.z, acc.z);
        acc.w = fmaf(xv, w.w, acc.w);
        Wp += N_SUB;
    }
    atomicAdd(&g_logits[col + 0], acc.x);
    atomicAdd(&g_logits[col + 1], acc.y);
    atomicAdd(&g_logits[col + 2], acc.z);
    atomicAdd(&g_logits[col + 3], acc.w);
}

// ---------------------------------------------------------------- finalize: value + softmax
__inline__ __device__ float warpSum(float v) {
#pragma unroll
    for (int o = 16; o; o >>= 1) v += __shfl_xor_sync(0xffffffffu, v, o);
    return v;
}
__inline__ __device__ float warpMax(float v) {
#pragma unroll
    for (int o = 16; o; o >>= 1) v = fmaxf(v, __shfl_xor_sync(0xffffffffu, v, o));
    return v;
}

__global__ void __launch_bounds__(1024)
k_final(const float* __restrict__ val_b,
        float* __restrict__ out, int out_size) {
    __shared__ float sred[32];
    __shared__ float svr[8];
    int t = threadIdx.x;
    int lane = t & 31, wid = t >> 5;

    if (t < VBLOCKS) {
        float x = g_vpart[t];
        x = warpSum(x);
        if (lane == 0) svr[wid] = x;
    }
    __syncthreads();
    if (t == 0 && out_size > N_SUB) {
        float v = val_b[0];
#pragma unroll
        for (int r = 0; r < 8; ++r) v += svr[r];
        out[N_SUB] = v;
    }
    __syncthreads();

    float l0 = g_logits[t];
    float l1 = g_logits[t + 1024];
    float l2 = g_logits[t + 2048];
    float l3 = g_logits[t + 3072];
    float m = fmaxf(fmaxf(l0, l1), fmaxf(l2, l3));
    m = warpMax(m);
    if (lane == 0) sred[wid] = m;
    __syncthreads();
    if (wid == 0) {
        float x = warpMax(sred[lane]);
        if (lane == 0) sred[0] = x;
    }
    __syncthreads();
    m = sred[0];
    __syncthreads();

    float e0 = expf(l0 - m), e1 = expf(l1 - m), e2 = expf(l2 - m), e3 = expf(l3 - m);
    float s = e0 + e1 + e2 + e3;
    s = warpSum(s);
    if (lane == 0) sred[wid] = s;
    __syncthreads();
    if (wid == 0) {
        float x = warpSum(sred[lane]);
        if (lane == 0) sred[0] = x;
    }
    __syncthreads();
    float inv = 1.0f / sred[0];

    out[t]        = e0 * inv;
    out[t + 1024] = e1 * inv;
    out[t + 2048] = e2 * inv;
    out[t + 3072] = e3 * inv;
}

// ---------------------------------------------------------------- PSS launch helper
template <typename F, typename... Args>
static inline void launch_pss(F f, dim3 g, dim3 b, Args... args) {
    cudaLaunchConfig_t cfg = {};
    cudaLaunchAttribute at[1];
    at[0].id = cudaLaunchAttributeProgrammaticStreamSerialization;
    at[0].val.programmaticStreamSerializationAllowed = 1;
    cfg.gridDim = g;
    cfg.blockDim = b;
    cfg.dynamicSmemBytes = 0;
    cfg.stream = 0;
    cfg.attrs = at;
    cfg.numAttrs = 1;
    cudaLaunchKernelEx(&cfg, f, args...);
}

// ----------------------------------------------------------------
extern "C" void kernel_launch(void* const* d_in, const int* in_sizes, int n_in,
                              void* d_out, int out_size) {
    const float* subs_x = (const float*)d_in[0];
    const float* vnr_x  = (const float*)d_in[1];
    const float* cheb_W = (const float*)d_in[2];
    const float* cheb_b = (const float*)d_in[3];
    const float* vnr_W  = (const float*)d_in[4];
    const float* vnr_b  = (const float*)d_in[5];
    const float* pol_W  = (const float*)d_in[6];
    const float* pol_b  = (const float*)d_in[7];
    const float* val_W  = (const float*)d_in[8];
    const float* val_b  = (const float*)d_in[9];
    const int*   ei     = (const int*)d_in[10];   // jax int64 w/o x64 -> int32
    const int*   perm   = (const int*)d_in[11];
    const int*   j_ptr  = (const int*)d_in[12];
    float* out = (float*)d_out;

    // Prefetch head of pol_W into L2; triggers at entry so the PSS prologue
    // overlaps with it. Every PSS kernel begins with
    // cudaGridDependencySynchronize(), restoring predecessor memory visibility
    // (this was the race in the previous round).
    k_prefetch<<<512, 256>>>(pol_W);

    launch_pss(k_zero,     dim3((N_SUB * 4 + 255) / 256), dim3(256), pol_b);
    launch_pss(k_deg,      dim3(N_EDGES / 256),           dim3(256), ei);
    launch_pss(k_lhat0,    dim3((N_EDGES * 4) / 256),     dim3(256), ei, subs_x);
    launch_pss(k_lhat1,    dim3((N_EDGES * 4) / 256),     dim3(256), ei);
    launch_pss(k_conv,     dim3(64), dim3(64), subs_x, cheb_W, cheb_b, vnr_x, vnr_W, vnr_b, j_ptr);
    launch_pss(k_fullyval, dim3(VBLOCKS), dim3(256), perm, val_W);

    // GEMV + final: normal launches -> wait for prefetch AND prologue.
    k_gemv <<<dim3(N_SUB / COLCHUNK, KBLOCKS), 256>>>(pol_W);
    k_final<<<1, 1024>>>(val_b, out, out_size);
}

// round 12
// speedup vs baseline: 1.0634x; 1.0634x over previous
#include <cuda_runtime.h>
#include <math.h>

#define N_SUB   4096
#define N_EDGES 65536
#define KTOT    65536          // 2*8*N_SUB
#define KBLOCKS 256            // GEMV k-chunks of 256 (2 waves -> work-steal balance)
#define KCHUNK  256
#define COLCHUNK 1024          // columns per GEMV block (256 thr * float4)
#define VBLOCKS 256            // fully/value blocks (256 elems each)

// ---- scratch (device globals; no allocation allowed) ----
__device__ float g_deg  [N_SUB];
__device__ float g_w    [N_EDGES];
__device__ float g_Tx1  [N_SUB * 4];
__device__ float g_Tx2  [N_SUB * 4];
__device__ float g_conv [N_SUB * 8];
__device__ float g_virt [8];
__device__ float g_fully[KTOT];
__device__ float g_logits[N_SUB];
__device__ float g_vpart[VBLOCKS];

// ---------------------------------------------------------------- zero + logits=bias
__global__ void k_zero(const float* __restrict__ pol_b) {
    int i = blockIdx.x * blockDim.x + threadIdx.x;
    if (i < N_SUB) { g_deg[i] = 0.f; g_logits[i] = pol_b[i]; }
    if (i < N_SUB * 4) { g_Tx1[i] = 0.f; g_Tx2[i] = 0.f; }
}

// ---------------------------------------------------------------- degree (1 edge/thread)
__global__ void k_deg(const int* __restrict__ ei) {
    int e = blockIdx.x * blockDim.x + threadIdx.x;
    if (e >= N_EDGES) return;
    int s = ei[e];
    if ((unsigned)s < N_SUB) atomicAdd(&g_deg[s], 1.0f);
}

// ---------------------------------------------------------------- L_hat stage 0
// 4 threads per edge; lane f==0 caches w[e] for stage 1.
__global__ void k_lhat0(const int* __restrict__ ei,
                        const float* __restrict__ subs_x) {
    int tid = blockIdx.x * blockDim.x + threadIdx.x;
    int e = tid >> 2, f = tid & 3;
    if (e >= N_EDGES) return;
    int s = ei[e];
    int d = ei[N_EDGES + e];
    bool ok = (unsigned)s < N_SUB && (unsigned)d < N_SUB;
    float w = 0.f;
    if (ok) {
        float ds = g_deg[s], dd = g_deg[d];
        if (ds > 0.f && dd > 0.f) w = -rsqrtf(ds) * rsqrtf(dd);
    }
    if (f == 0) g_w[e] = w;
    if (w != 0.f)
        atomicAdd(&g_Tx1[d * 4 + f], w * subs_x[s * 4 + f]);
}

// ---------------------------------------------------------------- L_hat stage 1 (cached w)
__global__ void k_lhat1(const int* __restrict__ ei) {
    int tid = blockIdx.x * blockDim.x + threadIdx.x;
    int e = tid >> 2, f = tid & 3;
    if (e >= N_EDGES) return;
    float w = g_w[e];
    if (w == 0.f) return;
    int s = ei[e];
    int d = ei[N_EDGES + e];
    atomicAdd(&g_Tx2[d * 4 + f], w * g_Tx1[s * 4 + f]);
}

// ---------------------------------------------------------------- conv + virt (1 node/thread, 64x64)
__global__ void k_conv(const float* __restrict__ subs_x,
                       const float* __restrict__ cheb_W,   // [3,4,8]
                       const float* __restrict__ cheb_b,   // [8]
                       const float* __restrict__ vnr_x,    // [5,2]
                       const float* __restrict__ vnr_W,    // [2,8]
                       const float* __restrict__ vnr_b,    // [8]
                       const int*   __restrict__ j_ptr) {
    __shared__ float sW[96], sb[8];
    int t = threadIdx.x;
    if (t < 8)  sb[t] = cheb_b[t];
    if (t < 64) { sW[t] = cheb_W[t]; if (t < 32) sW[64 + t] = cheb_W[64 + t]; }
    __syncthreads();

    if (blockIdx.x == 0 && t < 8) {
        int jj = j_ptr[0];
        if ((unsigned)jj >= 5u) jj = 0;
        g_virt[t] = vnr_x[jj * 2 + 0] * vnr_W[t] +
                    vnr_x[jj * 2 + 1] * vnr_W[8 + t] + vnr_b[t];
    }

    int n = blockIdx.x * blockDim.x + t;
    if (n >= N_SUB) return;
    float4 x0 = *reinterpret_cast<const float4*>(subs_x + n * 4);
    float4 x1 = *reinterpret_cast<const float4*>(g_Tx1 + n * 4);
    float4 a2 = *reinterpret_cast<const float4*>(g_Tx2 + n * 4);
    float t0[4] = { x0.x, x0.y, x0.z, x0.w };
    float t1[4] = { x1.x, x1.y, x1.z, x1.w };
    float t2[4] = { 2.f * a2.x - x0.x, 2.f * a2.y - x0.y,
                    2.f * a2.z - x0.z, 2.f * a2.w - x0.w };
#pragma unroll
    for (int o = 0; o < 8; ++o) {
        float s = sb[o];
#pragma unroll
        for (int f = 0; f < 4; ++f) {
            s = fmaf(t0[f], sW[f * 8 + o], s);
            s = fmaf(t1[f], sW[32 + f * 8 + o], s);
            s = fmaf(t2[f], sW[64 + f * 8 + o], s);
        }
        g_conv[n * 8 + o] = fmaxf(s, 0.f);
    }
}

// ---------------------------------------------------------------- perm gather + tanh + value partial dot
__global__ void k_fullyval(const int* __restrict__ perm,
                           const float* __restrict__ val_W) {
    __shared__ float sred[8];
    int t = threadIdx.x;
    int i = blockIdx.x * 256 + t;
    int p = perm[i] & (KTOT - 1);
    float v = (p < 8 * N_SUB) ? g_virt[p & 7] : g_conv[p - 8 * N_SUB];
    v = tanhf(v);
    g_fully[i] = v;
    float s = v * val_W[i];
#pragma unroll
    for (int o = 16; o; o >>= 1) s += __shfl_xor_sync(0xffffffffu, s, o);
    if ((t & 31) == 0) sred[t >> 5] = s;
    __syncthreads();
    if (t < 8) {
        float x = sred[t];
#pragma unroll
        for (int o = 4; o; o >>= 1) x += __shfl_xor_sync(0xffu, x, o);
        if (t == 0) g_vpart[blockIdx.x] = x;
    }
}

// ---------------------------------------------------------------- GEMV (accumulate into logits via RED)
// grid (4, 256), block 256.  Each block: cols [bx*1024,+1024), rows [by*256,+256).
// ~2 waves at occ 4 -> wave-2 work-stealing evens out L2-die / queue spread.
__global__ void __launch_bounds__(256, 4)
k_gemv(const float* __restrict__ W) {
    __shared__ float sx[KCHUNK];
    int t = threadIdx.x;
    int k0 = blockIdx.y * KCHUNK;
    int col = blockIdx.x * COLCHUNK + t * 4;
    sx[t] = g_fully[k0 + t];
    __syncthreads();

    const float* Wp = W + (size_t)k0 * N_SUB + col;
    float4 acc = make_float4(0.f, 0.f, 0.f, 0.f);
#pragma unroll 8
    for (int kk = 0; kk < KCHUNK; ++kk) {
        float xv = sx[kk];
        float4 w = __ldcs(reinterpret_cast<const float4*>(Wp));
        acc.x = fmaf(xv, w.x, acc.x);
        acc.y = fmaf(xv, w.y, acc.y);
        acc.z = fmaf(xv, w.z, acc.z);
        acc.w = fmaf(xv, w.w, acc.w);
        Wp += N_SUB;
    }
    atomicAdd(&g_logits[col + 0], acc.x);
    atomicAdd(&g_logits[col + 1], acc.y);
    atomicAdd(&g_logits[col + 2], acc.z);
    atomicAdd(&g_logits[col + 3], acc.w);
}

// ---------------------------------------------------------------- finalize: value + softmax
__inline__ __device__ float warpSum(float v) {
#pragma unroll
    for (int o = 16; o; o >>= 1) v += __shfl_xor_sync(0xffffffffu, v, o);
    return v;
}
__inline__ __device__ float warpMax(float v) {
#pragma unroll
    for (int o = 16; o; o >>= 1) v = fmaxf(v, __shfl_xor_sync(0xffffffffu, v, o));
    return v;
}

__global__ void __launch_bounds__(1024)
k_final(const float* __restrict__ val_b,
        float* __restrict__ out, int out_size) {
    __shared__ float sred[32];
    __shared__ float svr[8];
    int t = threadIdx.x;
    int lane = t & 31, wid = t >> 5;

    if (t < VBLOCKS) {
        float x = g_vpart[t];
        x = warpSum(x);
        if (lane == 0) svr[wid] = x;
    }
    __syncthreads();
    if (t == 0 && out_size > N_SUB) {
        float v = val_b[0];
#pragma unroll
        for (int r = 0; r < 8; ++r) v += svr[r];
        out[N_SUB] = v;
    }
    __syncthreads();

    float l0 = g_logits[t];
    float l1 = g_logits[t + 1024];
    float l2 = g_logits[t + 2048];
    float l3 = g_logits[t + 3072];
    float m = fmaxf(fmaxf(l0, l1), fmaxf(l2, l3));
    m = warpMax(m);
    if (lane == 0) sred[wid] = m;
    __syncthreads();
    if (wid == 0) {
        float x = warpMax(sred[lane]);
        if (lane == 0) sred[0] = x;
    }
    __syncthreads();
    m = sred[0];
    __syncthreads();

    float e0 = expf(l0 - m), e1 = expf(l1 - m), e2 = expf(l2 - m), e3 = expf(l3 - m);
    float s = e0 + e1 + e2 + e3;
    s = warpSum(s);
    if (lane == 0) sred[wid] = s;
    __syncthreads();
    if (wid == 0) {
        float x = warpSum(sred[lane]);
        if (lane == 0) sred[0] = x;
    }
    __syncthreads();
    float inv = 1.0f / sred[0];

    out[t]        = e0 * inv;
    out[t + 1024] = e1 * inv;
    out[t + 2048] = e2 * inv;
    out[t + 3072] = e3 * inv;
}

// ----------------------------------------------------------------
extern "C" void kernel_launch(void* const* d_in, const int* in_sizes, int n_in,
                              void* d_out, int out_size) {
    const float* subs_x = (const float*)d_in[0];
    const float* vnr_x  = (const float*)d_in[1];
    const float* cheb_W = (const float*)d_in[2];
    const float* cheb_b = (const float*)d_in[3];
    const float* vnr_W  = (const float*)d_in[4];
    const float* vnr_b  = (const float*)d_in[5];
    const float* pol_W  = (const float*)d_in[6];
    const float* pol_b  = (const float*)d_in[7];
    const float* val_W  = (const float*)d_in[8];
    const float* val_b  = (const float*)d_in[9];
    const int*   ei     = (const int*)d_in[10];   // jax int64 w/o x64 -> int32
    const int*   perm   = (const int*)d_in[11];
    const int*   j_ptr  = (const int*)d_in[12];
    float* out = (float*)d_out;

    k_zero    <<<(N_SUB * 4 + 255) / 256, 256>>>(pol_b);
    k_deg     <<<N_EDGES / 256, 256>>>(ei);
    k_lhat0   <<<(N_EDGES * 4) / 256, 256>>>(ei, subs_x);
    k_lhat1   <<<(N_EDGES * 4) / 256, 256>>>(ei);
    k_conv    <<<64, 64>>>(subs_x, cheb_W, cheb_b, vnr_x, vnr_W, vnr_b, j_ptr);
    k_fullyval<<<VBLOCKS, 256>>>(perm, val_W);
    k_gemv    <<<dim3(N_SUB / COLCHUNK, KBLOCKS), 256>>>(pol_W);
    k_final   <<<1, 1024>>>(val_b, out, out_size);
}